// round 2
// baseline (speedup 1.0000x reference)
#include <cuda_runtime.h>
#include <cuda_bf16.h>
#include <math.h>

// ---------------------------------------------------------------------------
// Transformer block, fp32, double-buffered SGEMM.
//   B=4, S=2048, D=1024, H=16, hd=64
// Pipeline:
//   qkv   = x @ Wqkv + bqkv                       [8192, 3072]
//   ctx   = causal_flash_attention(qkv)           [8192, 1024]
//   att   = ctx @ Wo + bo                         [8192, 1024]
//   h     = LN(att + x; g1,b1)                    [8192, 1024]
//   fc    = gelu(h @ Wfc + bfc)                   [8192, 4096]
//   m     = fc @ Wp + bp                          [8192, 1024]
//   out   = LN(m + h; g2,b2)                      [8192, 1024]
// ---------------------------------------------------------------------------

#define Mrows 8192
#define Dmod  1024
#define Seq   2048
#define Batch 4
#define Heads 16
#define HD    64

// Scratch (static device globals: allocation inside kernel_launch is forbidden)
__device__ float g_qkv[(size_t)Mrows * 3072];
__device__ float g_ctx[(size_t)Mrows * Dmod];
__device__ float g_att[(size_t)Mrows * Dmod];
__device__ float g_h  [(size_t)Mrows * Dmod];
__device__ float g_fc [(size_t)Mrows * 4096];
__device__ float g_m  [(size_t)Mrows * Dmod];

// ---------------------------------------------------------------------------
// SGEMM: C[M,N] = act(A[M,K] @ B[K,N] + bias[N])
// 128x128 tile, BK=8, 256 threads, 8x8 accum/thread, double-buffered smem.
// M,N multiples of 128; K multiple of 16.
// ---------------------------------------------------------------------------
template <bool DO_GELU>
__global__ __launch_bounds__(256)
void sgemm_bias_kernel(const float* __restrict__ A,
                       const float* __restrict__ B,
                       const float* __restrict__ bias,
                       float* __restrict__ C,
                       int M, int N, int K)
{
    __shared__ float As[2][8][128];
    __shared__ float Bs[2][8][128];

    const int bm = blockIdx.y * 128;
    const int bn = blockIdx.x * 128;
    const int tid = threadIdx.x;
    const int tx = tid & 15;        // 0..15 -> col group of 8
    const int ty = tid >> 4;        // 0..15 -> row group of 8

    // A-tile load mapping: 128 rows x 8 cols, one float4 per thread
    const int arow = tid >> 1;
    const int acol = (tid & 1) * 4;
    // B-tile load mapping: 8 rows x 128 cols, one float4 per thread
    const int brow = tid >> 5;
    const int bcol = (tid & 31) * 4;

    float acc[8][8];
#pragma unroll
    for (int i = 0; i < 8; i++)
#pragma unroll
        for (int j = 0; j < 8; j++) acc[i][j] = 0.f;

    const float* Aptr = A + (size_t)(bm + arow) * K + acol;
    const float* Bptr = B + (size_t)brow * N + bn + bcol;

    // prologue: load tile 0 into buffer 0
    {
        float4 av = *(const float4*)(Aptr);
        float4 bv = *(const float4*)(Bptr);
        As[0][acol + 0][arow] = av.x;
        As[0][acol + 1][arow] = av.y;
        As[0][acol + 2][arow] = av.z;
        As[0][acol + 3][arow] = av.w;
        *(float4*)&Bs[0][brow][bcol] = bv;
    }
    __syncthreads();

    for (int k0 = 0; k0 < K; k0 += 8) {
        const int rb = (k0 >> 3) & 1;   // read buffer
        const bool more = (k0 + 8) < K;

        // prefetch next tile into registers (overlaps with compute below)
        float4 av, bv;
        if (more) {
            av = *(const float4*)(Aptr + k0 + 8);
            bv = *(const float4*)(Bptr + (size_t)(k0 + 8) * N);
        }

#pragma unroll
        for (int kk = 0; kk < 8; kk++) {
            float4 a0 = *(const float4*)&As[rb][kk][ty * 8];
            float4 a1 = *(const float4*)&As[rb][kk][ty * 8 + 4];
            float4 b0 = *(const float4*)&Bs[rb][kk][tx * 8];
            float4 b1 = *(const float4*)&Bs[rb][kk][tx * 8 + 4];
            float a[8] = {a0.x, a0.y, a0.z, a0.w, a1.x, a1.y, a1.z, a1.w};
            float b[8] = {b0.x, b0.y, b0.z, b0.w, b1.x, b1.y, b1.z, b1.w};
#pragma unroll
            for (int i = 0; i < 8; i++)
#pragma unroll
                for (int j = 0; j < 8; j++)
                    acc[i][j] = fmaf(a[i], b[j], acc[i][j]);
        }

        if (more) {
            const int wb = rb ^ 1;
            As[wb][acol + 0][arow] = av.x;
            As[wb][acol + 1][arow] = av.y;
            As[wb][acol + 2][arow] = av.z;
            As[wb][acol + 3][arow] = av.w;
            *(float4*)&Bs[wb][brow][bcol] = bv;
            __syncthreads();
        }
    }

    // Epilogue: bias (+ exact GELU) and store
#pragma unroll
    for (int i = 0; i < 8; i++) {
        const int row = bm + ty * 8 + i;
        float* crow = C + (size_t)row * N + bn + tx * 8;
#pragma unroll
        for (int j = 0; j < 8; j++) {
            float v = acc[i][j] + bias[bn + tx * 8 + j];
            if (DO_GELU)
                v = 0.5f * v * (1.0f + erff(v * 0.70710678118654752440f));
            crow[j] = v;
        }
    }
}

// ---------------------------------------------------------------------------
// Causal flash attention (fp32).
// qkv layout: [B*S, 3072]; q at col h*64, k at 1024+h*64, v at 2048+h*64.
// One thread owns one query row (q[64], o[64] in registers).
// 128 threads/block = 128 query rows. K/V streamed in 64-row smem tiles.
// Grid: (S/128, H, B)
// ---------------------------------------------------------------------------
__global__ __launch_bounds__(128)
void flash_attn_kernel(const float* __restrict__ qkv, float* __restrict__ ctx)
{
    __shared__ float Ks[64][64];
    __shared__ float Vs[64][64];

    const int b = blockIdx.z;
    const int h = blockIdx.y;
    const int qrow = blockIdx.x * 128 + threadIdx.x;   // query index in S
    const float* base = qkv + (size_t)b * Seq * 3072;

    float q[HD];
    {
        const float4* qp = (const float4*)(base + (size_t)qrow * 3072 + h * HD);
#pragma unroll
        for (int j4 = 0; j4 < 16; j4++) {
            float4 v = qp[j4];
            q[4 * j4 + 0] = v.x; q[4 * j4 + 1] = v.y;
            q[4 * j4 + 2] = v.z; q[4 * j4 + 3] = v.w;
        }
    }

    float o[HD];
#pragma unroll
    for (int j = 0; j < HD; j++) o[j] = 0.f;
    float mmax = -INFINITY, lsum = 0.f;

    const int nkt = blockIdx.x * 2 + 2;   // key tiles covering keys <= max qrow

    for (int kt = 0; kt < nkt; kt++) {
        __syncthreads();   // protect previous tile from overwrite
        const int kb = kt * 64;
#pragma unroll
        for (int i = 0; i < 8; i++) {
            int lin = i * 128 + threadIdx.x;   // float4 index 0..1023
            int r = lin >> 4;
            int c = (lin & 15) * 4;
            const float* rowp = base + (size_t)(kb + r) * 3072 + h * HD;
            *(float4*)&Ks[r][c] = *(const float4*)(rowp + 1024 + c);
            *(float4*)&Vs[r][c] = *(const float4*)(rowp + 2048 + c);
        }
        __syncthreads();

#pragma unroll 1
        for (int k = 0; k < 64; k++) {
            const int key = kb + k;
            const float4* kr = (const float4*)&Ks[k][0];
            float s = 0.f;
#pragma unroll
            for (int j4 = 0; j4 < 16; j4++) {
                float4 kv = kr[j4];
                s = fmaf(q[4 * j4 + 0], kv.x, s);
                s = fmaf(q[4 * j4 + 1], kv.y, s);
                s = fmaf(q[4 * j4 + 2], kv.z, s);
                s = fmaf(q[4 * j4 + 3], kv.w, s);
            }
            s *= 0.125f;                        // 1/sqrt(64)
            s = (key <= qrow) ? s : -INFINITY;  // causal mask

            float mnew = fmaxf(mmax, s);
            if (mnew != mmax) {
                float corr = __expf(mmax - mnew);   // exp(-inf)=0 ok first key
                lsum *= corr;
#pragma unroll
                for (int j = 0; j < HD; j++) o[j] *= corr;
                mmax = mnew;
            }
            float p = __expf(s - mmax);
            lsum += p;
            const float4* vr = (const float4*)&Vs[k][0];
#pragma unroll
            for (int j4 = 0; j4 < 16; j4++) {
                float4 vv = vr[j4];
                o[4 * j4 + 0] = fmaf(p, vv.x, o[4 * j4 + 0]);
                o[4 * j4 + 1] = fmaf(p, vv.y, o[4 * j4 + 1]);
                o[4 * j4 + 2] = fmaf(p, vv.z, o[4 * j4 + 2]);
                o[4 * j4 + 3] = fmaf(p, vv.w, o[4 * j4 + 3]);
            }
        }
    }

    const float inv = 1.0f / lsum;
    float4* orow = (float4*)(ctx + (size_t)(b * Seq + qrow) * Dmod + h * HD);
#pragma unroll
    for (int j4 = 0; j4 < 16; j4++) {
        float4 w;
        w.x = o[4 * j4 + 0] * inv; w.y = o[4 * j4 + 1] * inv;
        w.z = o[4 * j4 + 2] * inv; w.w = o[4 * j4 + 3] * inv;
        orow[j4] = w;
    }
}

// ---------------------------------------------------------------------------
// Fused residual + LayerNorm: out = LN(a + r; g, beta)
// One block per row (D=1024), 256 threads, one float4 per thread.
// ---------------------------------------------------------------------------
__global__ __launch_bounds__(256)
void residual_ln_kernel(const float* __restrict__ A,
                        const float* __restrict__ R,
                        const float* __restrict__ g,
                        const float* __restrict__ beta,
                        float* __restrict__ out)
{
    const int row = blockIdx.x;
    const int t = threadIdx.x;
    const float4 a = ((const float4*)(A + (size_t)row * Dmod))[t];
    const float4 r = ((const float4*)(R + (size_t)row * Dmod))[t];
    float v0 = a.x + r.x, v1 = a.y + r.y, v2 = a.z + r.z, v3 = a.w + r.w;

    float s  = v0 + v1 + v2 + v3;
    float sq = v0 * v0 + v1 * v1 + v2 * v2 + v3 * v3;
#pragma unroll
    for (int off = 16; off > 0; off >>= 1) {
        s  += __shfl_xor_sync(0xFFFFFFFFu, s, off);
        sq += __shfl_xor_sync(0xFFFFFFFFu, sq, off);
    }
    __shared__ float ss[8], ssq[8];
    __shared__ float s_mu, s_rstd;
    const int wid = t >> 5;
    if ((t & 31) == 0) { ss[wid] = s; ssq[wid] = sq; }
    __syncthreads();
    if (t == 0) {
        float S = 0.f, SQ = 0.f;
#pragma unroll
        for (int i = 0; i < 8; i++) { S += ss[i]; SQ += ssq[i]; }
        float mu = S * (1.0f / Dmod);
        float var = SQ * (1.0f / Dmod) - mu * mu;
        s_mu = mu;
        s_rstd = rsqrtf(var + 1e-5f);
    }
    __syncthreads();
    const float mu = s_mu, rstd = s_rstd;

    const float4 G = ((const float4*)g)[t];
    const float4 Bt = ((const float4*)beta)[t];
    float4 w;
    w.x = (v0 - mu) * rstd * G.x + Bt.x;
    w.y = (v1 - mu) * rstd * G.y + Bt.y;
    w.z = (v2 - mu) * rstd * G.z + Bt.z;
    w.w = (v3 - mu) * rstd * G.w + Bt.w;
    ((float4*)(out + (size_t)row * Dmod))[t] = w;
}

// ---------------------------------------------------------------------------
// Launch
// Inputs (metadata order): 0 x, 1 mask, 2 Wqkv, 3 bqkv, 4 Wo, 5 bo,
//                          6 g1, 7 b1, 8 Wfc, 9 bfc, 10 Wp, 11 bp, 12 g2, 13 b2
// ---------------------------------------------------------------------------
extern "C" void kernel_launch(void* const* d_in, const int* in_sizes, int n_in,
                              void* d_out, int out_size)
{
    const float* x    = (const float*)d_in[0];
    const float* Wqkv = (const float*)d_in[2];
    const float* bqkv = (const float*)d_in[3];
    const float* Wo   = (const float*)d_in[4];
    const float* bo   = (const float*)d_in[5];
    const float* g1   = (const float*)d_in[6];
    const float* b1   = (const float*)d_in[7];
    const float* Wfc  = (const float*)d_in[8];
    const float* bfc  = (const float*)d_in[9];
    const float* Wp   = (const float*)d_in[10];
    const float* bp   = (const float*)d_in[11];
    const float* g2   = (const float*)d_in[12];
    const float* b2   = (const float*)d_in[13];
    float* out = (float*)d_out;

    float *qkv, *ctx, *att, *h, *fc, *m;
    cudaGetSymbolAddress((void**)&qkv, g_qkv);
    cudaGetSymbolAddress((void**)&ctx, g_ctx);
    cudaGetSymbolAddress((void**)&att, g_att);
    cudaGetSymbolAddress((void**)&h,   g_h);
    cudaGetSymbolAddress((void**)&fc,  g_fc);
    cudaGetSymbolAddress((void**)&m,   g_m);

    // 1) qkv = x @ Wqkv + bqkv        [8192,3072]
    sgemm_bias_kernel<false><<<dim3(3072 / 128, Mrows / 128), 256>>>(
        x, Wqkv, bqkv, qkv, Mrows, 3072, Dmod);

    // 2) ctx = attention(qkv)         [8192,1024]
    flash_attn_kernel<<<dim3(Seq / 128, Heads, Batch), 128>>>(qkv, ctx);

    // 3) att = ctx @ Wo + bo          [8192,1024]
    sgemm_bias_kernel<false><<<dim3(Dmod / 128, Mrows / 128), 256>>>(
        ctx, Wo, bo, att, Mrows, Dmod, Dmod);

    // 4) h = LN(att + x)
    residual_ln_kernel<<<Mrows, 256>>>(att, x, g1, b1, h);

    // 5) fc = gelu(h @ Wfc + bfc)     [8192,4096]
    sgemm_bias_kernel<true><<<dim3(4096 / 128, Mrows / 128), 256>>>(
        h, Wfc, bfc, fc, Mrows, 4096, Dmod);

    // 6) m = fc @ Wp + bp             [8192,1024]
    sgemm_bias_kernel<false><<<dim3(Dmod / 128, Mrows / 128), 256>>>(
        fc, Wp, bp, m, Mrows, Dmod, 4096);

    // 7) out = LN(m + h)
    residual_ln_kernel<<<Mrows, 256>>>(m, h, g2, b2, out);
}

// round 5
// speedup vs baseline: 1.8333x; 1.8333x over previous
#include <cuda_runtime.h>
#include <cuda_bf16.h>
#include <math.h>
#include <stdint.h>

// ---------------------------------------------------------------------------
// Transformer block. GEMMs on mma.sync bf16 (split hi/lo, fp32 accumulate),
// flash attention fp32, fused residual+LN.  Target: plain sm_100 (no tcgen05).
//   B=4, S=2048, D=1024, H=16, hd=64
// ---------------------------------------------------------------------------

#define Mrows 8192
#define Dmod  1024
#define Seq   2048
#define Batch 4
#define Heads 16
#define HD    64

// ---------------- scratch (device globals; no allocs allowed) --------------
__device__ float g_qkv[(size_t)Mrows * 3072];
__device__ float g_att[(size_t)Mrows * Dmod];
__device__ float g_h  [(size_t)Mrows * Dmod];
__device__ float g_m  [(size_t)Mrows * Dmod];

__device__ __nv_bfloat16 g_xhi[(size_t)Mrows * 1024];
__device__ __nv_bfloat16 g_xlo[(size_t)Mrows * 1024];
__device__ __nv_bfloat16 g_ctxhi[(size_t)Mrows * 1024];
__device__ __nv_bfloat16 g_ctxlo[(size_t)Mrows * 1024];
__device__ __nv_bfloat16 g_hhi[(size_t)Mrows * 1024];
__device__ __nv_bfloat16 g_hlo[(size_t)Mrows * 1024];
__device__ __nv_bfloat16 g_fchi[(size_t)Mrows * 4096];
__device__ __nv_bfloat16 g_fclo[(size_t)Mrows * 4096];

// transposed weights, [N,K] K-major
__device__ __nv_bfloat16 g_wqkvThi[(size_t)3072 * 1024];
__device__ __nv_bfloat16 g_wqkvTlo[(size_t)3072 * 1024];
__device__ __nv_bfloat16 g_woThi[(size_t)1024 * 1024];
__device__ __nv_bfloat16 g_woTlo[(size_t)1024 * 1024];
__device__ __nv_bfloat16 g_wfcThi[(size_t)4096 * 1024];
__device__ __nv_bfloat16 g_wfcTlo[(size_t)4096 * 1024];
__device__ __nv_bfloat16 g_wpThi[(size_t)1024 * 4096];
__device__ __nv_bfloat16 g_wpTlo[(size_t)1024 * 4096];

// ---------------- PTX helpers ----------------------------------------------
__device__ __forceinline__ uint32_t smem_u32(const void* p) {
    uint32_t a;
    asm("{ .reg .u64 t; cvta.to.shared.u64 t, %1; cvt.u32.u64 %0, t; }"
        : "=r"(a) : "l"(p));
    return a;
}

#define CP_ASYNC16(smem, gptr) \
    asm volatile("cp.async.cg.shared.global [%0], [%1], 16;" \
                 :: "r"(smem), "l"(gptr) : "memory")
#define CP_COMMIT() asm volatile("cp.async.commit_group;" ::: "memory")
#define CP_WAIT(n)  asm volatile("cp.async.wait_group %0;" :: "n"(n) : "memory")

#define LDSM_X4(r0, r1, r2, r3, addr) \
    asm volatile("ldmatrix.sync.aligned.m8n8.x4.shared.b16 {%0,%1,%2,%3}, [%4];" \
                 : "=r"(r0), "=r"(r1), "=r"(r2), "=r"(r3) : "r"(addr))
#define LDSM_X2(r0, r1, addr) \
    asm volatile("ldmatrix.sync.aligned.m8n8.x2.shared.b16 {%0,%1}, [%2];" \
                 : "=r"(r0), "=r"(r1) : "r"(addr))

__device__ __forceinline__ void mma_bf16(float* d, const uint32_t* a, const uint32_t* b) {
    asm volatile(
        "mma.sync.aligned.m16n8k16.row.col.f32.bf16.bf16.f32 "
        "{%0,%1,%2,%3}, {%4,%5,%6,%7}, {%8,%9}, {%0,%1,%2,%3};"
        : "+f"(d[0]), "+f"(d[1]), "+f"(d[2]), "+f"(d[3])
        : "r"(a[0]), "r"(a[1]), "r"(a[2]), "r"(a[3]), "r"(b[0]), "r"(b[1]));
}

// ---------------- bf16 split helpers ---------------------------------------
__device__ __forceinline__ void split2(float a, float b, uint32_t& hi, uint32_t& lo) {
    __nv_bfloat16 ha = __float2bfloat16(a), hb = __float2bfloat16(b);
    hi = (uint32_t)__bfloat16_as_ushort(ha) | ((uint32_t)__bfloat16_as_ushort(hb) << 16);
    float la = a - __bfloat162float(ha);
    float lb = b - __bfloat162float(hb);
    __nv_bfloat16 hla = __float2bfloat16(la), hlb = __float2bfloat16(lb);
    lo = (uint32_t)__bfloat16_as_ushort(hla) | ((uint32_t)__bfloat16_as_ushort(hlb) << 16);
}

// ---------------------------------------------------------------------------
// Pre-pass: elementwise split of x (row-major [M,K] preserved)
// ---------------------------------------------------------------------------
__global__ __launch_bounds__(256)
void xsplit_kernel(const float4* __restrict__ src, uint2* __restrict__ hi,
                   uint2* __restrict__ lo, int n4)
{
    int i = blockIdx.x * 256 + threadIdx.x;
    if (i >= n4) return;
    float4 v = src[i];
    uint32_t h0, l0, h1, l1;
    split2(v.x, v.y, h0, l0);
    split2(v.z, v.w, h1, l1);
    hi[i] = make_uint2(h0, h1);
    lo[i] = make_uint2(l0, l1);
}

// ---------------------------------------------------------------------------
// Pre-pass: weight transpose + split. src [K,N] fp32 -> dst [N,K] bf16 hi/lo.
// ---------------------------------------------------------------------------
__global__ __launch_bounds__(256)
void wsplit_kernel(const float* __restrict__ src, __nv_bfloat16* __restrict__ dhi,
                   __nv_bfloat16* __restrict__ dlo, int K, int N)
{
    __shared__ float t[32][33];
    const int k0 = blockIdx.x * 32, n0 = blockIdx.y * 32;
    const int tx = threadIdx.x & 31, ty = threadIdx.x >> 5;   // 32x8
#pragma unroll
    for (int i = 0; i < 4; i++)
        t[ty + i * 8][tx] = src[(size_t)(k0 + ty + i * 8) * N + n0 + tx];
    __syncthreads();
    const int kp = threadIdx.x & 15, nb = threadIdx.x >> 4;   // 16x16
#pragma unroll
    for (int i = 0; i < 2; i++) {
        const int nn = nb + i * 16;
        float v0 = t[2 * kp][nn], v1 = t[2 * kp + 1][nn];
        uint32_t h, l;
        split2(v0, v1, h, l);
        const size_t u32i = ((size_t)(n0 + nn) * K + k0) / 2 + kp;
        ((uint32_t*)dhi)[u32i] = h;
        ((uint32_t*)dlo)[u32i] = l;
    }
}

// ---------------------------------------------------------------------------
// HMMA split-bf16 GEMM: C[M,N] = act(A @ Bt^T + bias)
//   A hi/lo: [M,K] row-major bf16.  Bt hi/lo: [N,K] row-major bf16.
//   128x128 block tile, BK=32, 256 threads (2x4 warps, 64x32 warp tile).
//   cp.async double-buffered smem; 3 mma passes: AhiBhi + AhiBlo + AloBhi.
// Smem tile rows are padded to 40 bf16 (80 B): 8-row ldmatrix phases hit
// banks {0,20,8,28,16,4,24,12} - conflict-free.
// ---------------------------------------------------------------------------
#define TILE_BYTES 10240              // 128 rows * 80 B
#define OFF_AH 0
#define OFF_AL 10240
#define OFF_BH 20480
#define OFF_BL 30720
#define STAGE_BYTES 40960

__device__ __forceinline__ void fill_tile_async(uint32_t dst,
                                                const __nv_bfloat16* __restrict__ src,
                                                int row0, int ld, int k0, int tid)
{
#pragma unroll
    for (int half = 0; half < 2; half++) {
        const int i = half * 256 + tid;        // 0..511 uint4 chunks
        const int r = i >> 2;
        const int c16 = (i & 3) * 8;           // bf16 col offset
        const uint32_t s = dst + (uint32_t)(r * 80 + c16 * 2);
        const __nv_bfloat16* g = src + (size_t)(row0 + r) * ld + k0 + c16;
        CP_ASYNC16(s, g);
    }
}

template <bool DO_GELU, bool OUT_F32, bool OUT_BF16>
__global__ __launch_bounds__(256)
void gemm_hmma_kernel(const __nv_bfloat16* __restrict__ Ahi, const __nv_bfloat16* __restrict__ Alo,
                      const __nv_bfloat16* __restrict__ Bhi, const __nv_bfloat16* __restrict__ Blo,
                      const float* __restrict__ bias,
                      float* __restrict__ Cf,
                      __nv_bfloat16* __restrict__ Chi, __nv_bfloat16* __restrict__ Clo,
                      int M, int N, int K)
{
    extern __shared__ char dynsmem[];
    const uint32_t base = smem_u32(dynsmem);

    const int tid = threadIdx.x;
    const int wid = tid >> 5;
    const int lane = tid & 31;
    const int bm = blockIdx.y * 128;
    const int bn = blockIdx.x * 128;
    const int warp_m = (wid >> 2) * 64;     // 2 warps over M
    const int warp_n = (wid & 3) * 32;      // 4 warps over N

    float acc[4][4][4];
#pragma unroll
    for (int mi = 0; mi < 4; mi++)
#pragma unroll
        for (int ni = 0; ni < 4; ni++)
#pragma unroll
            for (int r = 0; r < 4; r++) acc[mi][ni][r] = 0.f;

    const int nch = K >> 5;

    // prologue: stage 0
    {
        const uint32_t st = base;
        fill_tile_async(st + OFF_AH, Ahi, bm, K, 0, tid);
        fill_tile_async(st + OFF_AL, Alo, bm, K, 0, tid);
        fill_tile_async(st + OFF_BH, Bhi, bn, K, 0, tid);
        fill_tile_async(st + OFF_BL, Blo, bn, K, 0, tid);
        CP_COMMIT();
    }

    // ldmatrix lane addressing (constant across chunks)
    const int a_row = lane & 15;
    const int a_col8 = (lane >> 4) * 8;          // 0 or 8
    const int b_row = lane & 7;
    const int b_col8 = ((lane >> 3) & 1) * 8;    // 0 or 8 (lanes 0..15 matter)

    for (int c = 0; c < nch; ++c) {
        if (c + 1 < nch) {
            const uint32_t st = base + ((c + 1) & 1) * STAGE_BYTES;
            const int k0 = (c + 1) << 5;
            fill_tile_async(st + OFF_AH, Ahi, bm, K, k0, tid);
            fill_tile_async(st + OFF_AL, Alo, bm, K, k0, tid);
            fill_tile_async(st + OFF_BH, Bhi, bn, K, k0, tid);
            fill_tile_async(st + OFF_BL, Blo, bn, K, k0, tid);
            CP_COMMIT();
            CP_WAIT(1);
        } else {
            CP_WAIT(0);
        }
        __syncthreads();

        const uint32_t st = base + (c & 1) * STAGE_BYTES;
#pragma unroll
        for (int kf = 0; kf < 2; kf++) {
            uint32_t ah[4][4], al[4][4], bh[4][2], bl[4][2];
            const int kc = kf * 16;
#pragma unroll
            for (int mi = 0; mi < 4; mi++) {
                const uint32_t roff = (uint32_t)((warp_m + mi * 16 + a_row) * 80 + (kc + a_col8) * 2);
                LDSM_X4(ah[mi][0], ah[mi][1], ah[mi][2], ah[mi][3], st + OFF_AH + roff);
                LDSM_X4(al[mi][0], al[mi][1], al[mi][2], al[mi][3], st + OFF_AL + roff);
            }
#pragma unroll
            for (int ni = 0; ni < 4; ni++) {
                const uint32_t roff = (uint32_t)((warp_n + ni * 8 + b_row) * 80 + (kc + b_col8) * 2);
                LDSM_X2(bh[ni][0], bh[ni][1], st + OFF_BH + roff);
                LDSM_X2(bl[ni][0], bl[ni][1], st + OFF_BL + roff);
            }
#pragma unroll
            for (int mi = 0; mi < 4; mi++)
#pragma unroll
                for (int ni = 0; ni < 4; ni++) {
                    mma_bf16(acc[mi][ni], ah[mi], bh[ni]);
                    mma_bf16(acc[mi][ni], ah[mi], bl[ni]);
                    mma_bf16(acc[mi][ni], al[mi], bh[ni]);
                }
        }
        __syncthreads();
    }

    // epilogue: acc layout c0,c1 @ (r, c..c+1), c2,c3 @ (r+8, c..c+1)
    const int er = lane >> 2;
    const int ec = (lane & 3) * 2;
#pragma unroll
    for (int ni = 0; ni < 4; ni++) {
        const int col = bn + warp_n + ni * 8 + ec;
        const float2 bv = *(const float2*)(bias + col);
#pragma unroll
        for (int mi = 0; mi < 4; mi++) {
            const int row = bm + warp_m + mi * 16 + er;
            float v00 = acc[mi][ni][0] + bv.x;
            float v01 = acc[mi][ni][1] + bv.y;
            float v10 = acc[mi][ni][2] + bv.x;
            float v11 = acc[mi][ni][3] + bv.y;
            if (DO_GELU) {
                v00 = 0.5f * v00 * (1.0f + erff(v00 * 0.70710678118654752440f));
                v01 = 0.5f * v01 * (1.0f + erff(v01 * 0.70710678118654752440f));
                v10 = 0.5f * v10 * (1.0f + erff(v10 * 0.70710678118654752440f));
                v11 = 0.5f * v11 * (1.0f + erff(v11 * 0.70710678118654752440f));
            }
            if (OUT_F32) {
                *(float2*)(Cf + (size_t)row * N + col)       = make_float2(v00, v01);
                *(float2*)(Cf + (size_t)(row + 8) * N + col) = make_float2(v10, v11);
            }
            if (OUT_BF16) {
                uint32_t h0, l0, h1, l1;
                split2(v00, v01, h0, l0);
                split2(v10, v11, h1, l1);
                *(uint32_t*)(Chi + (size_t)row * N + col)       = h0;
                *(uint32_t*)(Clo + (size_t)row * N + col)       = l0;
                *(uint32_t*)(Chi + (size_t)(row + 8) * N + col) = h1;
                *(uint32_t*)(Clo + (size_t)(row + 8) * N + col) = l1;
            }
        }
    }
}

// ---------------------------------------------------------------------------
// Causal flash attention (fp32 compute), emits ctx as split bf16.
// ---------------------------------------------------------------------------
__global__ __launch_bounds__(128)
void flash_attn_kernel(const float* __restrict__ qkv,
                       __nv_bfloat16* __restrict__ ctxhi,
                       __nv_bfloat16* __restrict__ ctxlo)
{
    __shared__ float Ks[64][64];
    __shared__ float Vs[64][64];

    const int b = blockIdx.z;
    const int h = blockIdx.y;
    const int qrow = blockIdx.x * 128 + threadIdx.x;
    const float* base = qkv + (size_t)b * Seq * 3072;

    float q[HD];
    {
        const float4* qp = (const float4*)(base + (size_t)qrow * 3072 + h * HD);
#pragma unroll
        for (int j4 = 0; j4 < 16; j4++) {
            float4 v = qp[j4];
            q[4 * j4 + 0] = v.x; q[4 * j4 + 1] = v.y;
            q[4 * j4 + 2] = v.z; q[4 * j4 + 3] = v.w;
        }
    }

    float o[HD];
#pragma unroll
    for (int j = 0; j < HD; j++) o[j] = 0.f;
    float mmax = -INFINITY, lsum = 0.f;

    const int nkt = blockIdx.x * 2 + 2;

    for (int kt = 0; kt < nkt; kt++) {
        __syncthreads();
        const int kb = kt * 64;
#pragma unroll
        for (int i = 0; i < 8; i++) {
            int lin = i * 128 + threadIdx.x;
            int r = lin >> 4;
            int c = (lin & 15) * 4;
            const float* rowp = base + (size_t)(kb + r) * 3072 + h * HD;
            *(float4*)&Ks[r][c] = *(const float4*)(rowp + 1024 + c);
            *(float4*)&Vs[r][c] = *(const float4*)(rowp + 2048 + c);
        }
        __syncthreads();

#pragma unroll 1
        for (int k = 0; k < 64; k++) {
            const int key = kb + k;
            const float4* kr = (const float4*)&Ks[k][0];
            float s = 0.f;
#pragma unroll
            for (int j4 = 0; j4 < 16; j4++) {
                float4 kv = kr[j4];
                s = fmaf(q[4 * j4 + 0], kv.x, s);
                s = fmaf(q[4 * j4 + 1], kv.y, s);
                s = fmaf(q[4 * j4 + 2], kv.z, s);
                s = fmaf(q[4 * j4 + 3], kv.w, s);
            }
            s *= 0.125f;
            s = (key <= qrow) ? s : -INFINITY;

            float mnew = fmaxf(mmax, s);
            if (mnew != mmax) {
                float corr = __expf(mmax - mnew);
                lsum *= corr;
#pragma unroll
                for (int j = 0; j < HD; j++) o[j] *= corr;
                mmax = mnew;
            }
            float p = __expf(s - mmax);
            lsum += p;
            const float4* vr = (const float4*)&Vs[k][0];
#pragma unroll
            for (int j4 = 0; j4 < 16; j4++) {
                float4 vv = vr[j4];
                o[4 * j4 + 0] = fmaf(p, vv.x, o[4 * j4 + 0]);
                o[4 * j4 + 1] = fmaf(p, vv.y, o[4 * j4 + 1]);
                o[4 * j4 + 2] = fmaf(p, vv.z, o[4 * j4 + 2]);
                o[4 * j4 + 3] = fmaf(p, vv.w, o[4 * j4 + 3]);
            }
        }
    }

    const float inv = 1.0f / lsum;
    uint32_t hi[32], lo[32];
#pragma unroll
    for (int j = 0; j < 32; j++)
        split2(o[2 * j] * inv, o[2 * j + 1] * inv, hi[j], lo[j]);

    const size_t off = (size_t)(b * Seq + qrow) * Dmod + h * HD;
    uint4* ph = (uint4*)(ctxhi + off);
    uint4* pl = (uint4*)(ctxlo + off);
#pragma unroll
    for (int j = 0; j < 8; j++) {
        ph[j] = make_uint4(hi[4 * j], hi[4 * j + 1], hi[4 * j + 2], hi[4 * j + 3]);
        pl[j] = make_uint4(lo[4 * j], lo[4 * j + 1], lo[4 * j + 2], lo[4 * j + 3]);
    }
}

// ---------------------------------------------------------------------------
// Fused residual + LayerNorm. Optionally also emits split bf16 of the result.
// ---------------------------------------------------------------------------
template <bool EMIT_SPLIT>
__global__ __launch_bounds__(256)
void residual_ln_kernel(const float* __restrict__ A,
                        const float* __restrict__ R,
                        const float* __restrict__ g,
                        const float* __restrict__ beta,
                        float* __restrict__ out,
                        __nv_bfloat16* __restrict__ ohi,
                        __nv_bfloat16* __restrict__ olo)
{
    const int row = blockIdx.x;
    const int t = threadIdx.x;
    const float4 a = ((const float4*)(A + (size_t)row * Dmod))[t];
    const float4 r = ((const float4*)(R + (size_t)row * Dmod))[t];
    float v0 = a.x + r.x, v1 = a.y + r.y, v2 = a.z + r.z, v3 = a.w + r.w;

    float s  = v0 + v1 + v2 + v3;
    float sq = v0 * v0 + v1 * v1 + v2 * v2 + v3 * v3;
#pragma unroll
    for (int off = 16; off > 0; off >>= 1) {
        s  += __shfl_xor_sync(0xFFFFFFFFu, s, off);
        sq += __shfl_xor_sync(0xFFFFFFFFu, sq, off);
    }
    __shared__ float ss[8], ssq[8];
    __shared__ float s_mu, s_rstd;
    const int wid = t >> 5;
    if ((t & 31) == 0) { ss[wid] = s; ssq[wid] = sq; }
    __syncthreads();
    if (t == 0) {
        float S = 0.f, SQ = 0.f;
#pragma unroll
        for (int i = 0; i < 8; i++) { S += ss[i]; SQ += ssq[i]; }
        float mu = S * (1.0f / Dmod);
        float var = SQ * (1.0f / Dmod) - mu * mu;
        s_mu = mu;
        s_rstd = rsqrtf(var + 1e-5f);
    }
    __syncthreads();
    const float mu = s_mu, rstd = s_rstd;

    const float4 G = ((const float4*)g)[t];
    const float4 Bt = ((const float4*)beta)[t];
    float4 w;
    w.x = (v0 - mu) * rstd * G.x + Bt.x;
    w.y = (v1 - mu) * rstd * G.y + Bt.y;
    w.z = (v2 - mu) * rstd * G.z + Bt.z;
    w.w = (v3 - mu) * rstd * G.w + Bt.w;
    ((float4*)(out + (size_t)row * Dmod))[t] = w;

    if (EMIT_SPLIT) {
        uint32_t h0, l0, h1, l1;
        split2(w.x, w.y, h0, l0);
        split2(w.z, w.w, h1, l1);
        ((uint2*)ohi)[(size_t)row * 256 + t] = make_uint2(h0, h1);
        ((uint2*)olo)[(size_t)row * 256 + t] = make_uint2(l0, l1);
    }
}

// ---------------------------------------------------------------------------
// Launch
// Inputs: 0 x, 1 mask, 2 Wqkv, 3 bqkv, 4 Wo, 5 bo, 6 g1, 7 b1,
//         8 Wfc, 9 bfc, 10 Wp, 11 bp, 12 g2, 13 b2
// ---------------------------------------------------------------------------
extern "C" void kernel_launch(void* const* d_in, const int* in_sizes, int n_in,
                              void* d_out, int out_size)
{
    const float* x    = (const float*)d_in[0];
    const float* Wqkv = (const float*)d_in[2];
    const float* bqkv = (const float*)d_in[3];
    const float* Wo   = (const float*)d_in[4];
    const float* bo   = (const float*)d_in[5];
    const float* g1   = (const float*)d_in[6];
    const float* b1   = (const float*)d_in[7];
    const float* Wfc  = (const float*)d_in[8];
    const float* bfc  = (const float*)d_in[9];
    const float* Wp   = (const float*)d_in[10];
    const float* bp   = (const float*)d_in[11];
    const float* g2   = (const float*)d_in[12];
    const float* b2   = (const float*)d_in[13];
    float* out = (float*)d_out;

    float *qkv, *att, *h, *m;
    cudaGetSymbolAddress((void**)&qkv, g_qkv);
    cudaGetSymbolAddress((void**)&att, g_att);
    cudaGetSymbolAddress((void**)&h,   g_h);
    cudaGetSymbolAddress((void**)&m,   g_m);

    __nv_bfloat16 *xhi, *xlo, *ctxhi, *ctxlo, *hhi, *hlo, *fchi, *fclo;
    __nv_bfloat16 *wqkvThi, *wqkvTlo, *woThi, *woTlo, *wfcThi, *wfcTlo, *wpThi, *wpTlo;
    cudaGetSymbolAddress((void**)&xhi, g_xhi);       cudaGetSymbolAddress((void**)&xlo, g_xlo);
    cudaGetSymbolAddress((void**)&ctxhi, g_ctxhi);   cudaGetSymbolAddress((void**)&ctxlo, g_ctxlo);
    cudaGetSymbolAddress((void**)&hhi, g_hhi);       cudaGetSymbolAddress((void**)&hlo, g_hlo);
    cudaGetSymbolAddress((void**)&fchi, g_fchi);     cudaGetSymbolAddress((void**)&fclo, g_fclo);
    cudaGetSymbolAddress((void**)&wqkvThi, g_wqkvThi); cudaGetSymbolAddress((void**)&wqkvTlo, g_wqkvTlo);
    cudaGetSymbolAddress((void**)&woThi, g_woThi);   cudaGetSymbolAddress((void**)&woTlo, g_woTlo);
    cudaGetSymbolAddress((void**)&wfcThi, g_wfcThi); cudaGetSymbolAddress((void**)&wfcTlo, g_wfcTlo);
    cudaGetSymbolAddress((void**)&wpThi, g_wpThi);   cudaGetSymbolAddress((void**)&wpTlo, g_wpTlo);

    const int smem_bytes = 2 * STAGE_BYTES;
    cudaFuncSetAttribute(gemm_hmma_kernel<false, true, false>,
                         cudaFuncAttributeMaxDynamicSharedMemorySize, smem_bytes);
    cudaFuncSetAttribute(gemm_hmma_kernel<true, false, true>,
                         cudaFuncAttributeMaxDynamicSharedMemorySize, smem_bytes);

    // --- pre-pass: split x and weights --------------------------------------
    xsplit_kernel<<<(Mrows * 1024 / 4 + 255) / 256, 256>>>(
        (const float4*)x, (uint2*)xhi, (uint2*)xlo, Mrows * 1024 / 4);
    wsplit_kernel<<<dim3(1024 / 32, 3072 / 32), 256>>>(Wqkv, wqkvThi, wqkvTlo, 1024, 3072);
    wsplit_kernel<<<dim3(1024 / 32, 1024 / 32), 256>>>(Wo,   woThi,   woTlo,   1024, 1024);
    wsplit_kernel<<<dim3(1024 / 32, 4096 / 32), 256>>>(Wfc,  wfcThi,  wfcTlo,  1024, 4096);
    wsplit_kernel<<<dim3(4096 / 32, 1024 / 32), 256>>>(Wp,   wpThi,   wpTlo,   4096, 1024);

    // 1) qkv = x @ Wqkv + bqkv     [8192,3072] fp32
    gemm_hmma_kernel<false, true, false><<<dim3(3072 / 128, Mrows / 128), 256, smem_bytes>>>(
        xhi, xlo, wqkvThi, wqkvTlo, bqkv, qkv, nullptr, nullptr, Mrows, 3072, 1024);

    // 2) ctx = attention(qkv)      -> split bf16
    flash_attn_kernel<<<dim3(Seq / 128, Heads, Batch), 128>>>(qkv, ctxhi, ctxlo);

    // 3) att = ctx @ Wo + bo       [8192,1024] fp32
    gemm_hmma_kernel<false, true, false><<<dim3(1024 / 128, Mrows / 128), 256, smem_bytes>>>(
        ctxhi, ctxlo, woThi, woTlo, bo, att, nullptr, nullptr, Mrows, 1024, 1024);

    // 4) h = LN(att + x)           fp32 + split bf16
    residual_ln_kernel<true><<<Mrows, 256>>>(att, x, g1, b1, h, hhi, hlo);

    // 5) fc = gelu(h @ Wfc + bfc)  -> split bf16
    gemm_hmma_kernel<true, false, true><<<dim3(4096 / 128, Mrows / 128), 256, smem_bytes>>>(
        hhi, hlo, wfcThi, wfcTlo, bfc, nullptr, fchi, fclo, Mrows, 4096, 1024);

    // 6) m = fc @ Wp + bp          [8192,1024] fp32
    gemm_hmma_kernel<false, true, false><<<dim3(1024 / 128, Mrows / 128), 256, smem_bytes>>>(
        fchi, fclo, wpThi, wpTlo, bp, m, nullptr, nullptr, Mrows, 1024, 4096);

    // 7) out = LN(m + h)
    residual_ln_kernel<false><<<Mrows, 256>>>(m, h, g2, b2, out, nullptr, nullptr);
}